// round 9
// baseline (speedup 1.0000x reference)
#include <cuda_runtime.h>
#include <cuda_bf16.h>
#include <math.h>
#include <stdint.h>

// ---------------------------------------------------------------------------
// BitNet b1.58 MLP, exact-integer formulation on legacy bf16 HMMA.
// R8 -> R9: ldmatrix.x4 fragments, warp tile 64x64, fused gate+up kernel
// (silu exchange via smem), vectorized quant kernels, fp32-partial absum.
// Arithmetic identical to R8 (rel_err 5.6487e-4): codes/weights exact in
// bf16, fp32 accum of ints < 2^24 exact.
// ---------------------------------------------------------------------------

#define Dd 2048
#define Ff 8192
#define Mm 4096

#define ROWB 144                 // 64 bf16 = 128B data + 16B pad
#define STG  55296               // 384 rows * 144B per pipeline stage
#define GEMM_SMEM (3 * STG)      // 165888

__device__ __align__(128) __nv_bfloat16 g_wgb[Ff * Dd];
__device__ __align__(128) __nv_bfloat16 g_wub[Ff * Dd];
__device__ __align__(128) __nv_bfloat16 g_wdb[Dd * Ff];
__device__ __align__(128) __nv_bfloat16 g_xb[Mm * Dd];
__device__ __align__(128) __nv_bfloat16 g_hb[(size_t)Mm * Ff];
__device__ __align__(128) float g_H[(size_t)Mm * Ff];
__device__ float  g_xdq[Mm];
__device__ float  g_hdq[Mm];
__device__ double g_wsum[3];
__device__ float  g_wdq[3];

// ------------------------------ utilities ----------------------------------

__device__ __forceinline__ uint32_t smem_u32(const void* p) {
    uint32_t a;
    asm("{ .reg .u64 t; cvta.to.shared.u64 t, %1; cvt.u32.u64 %0, t; }"
        : "=r"(a) : "l"(p));
    return a;
}
__device__ __forceinline__ void cp16(uint32_t dst, const void* src) {
    asm volatile("cp.async.cg.shared.global [%0], [%1], 16;"
                 :: "r"(dst), "l"(src) : "memory");
}
__device__ __forceinline__ void cp_commit() {
    asm volatile("cp.async.commit_group;" ::: "memory");
}
__device__ __forceinline__ void cp_wait1() {
    asm volatile("cp.async.wait_group 1;" ::: "memory");
}
__device__ __forceinline__ void ldsm4(uint32_t* r, uint32_t addr) {
    asm volatile("ldmatrix.sync.aligned.m8n8.x4.shared.b16 {%0,%1,%2,%3}, [%4];"
                 : "=r"(r[0]), "=r"(r[1]), "=r"(r[2]), "=r"(r[3]) : "r"(addr));
}
__device__ __forceinline__ void mma_bf16(float* c, const uint32_t* a, const uint32_t* b) {
    asm volatile(
        "mma.sync.aligned.m16n8k16.row.col.f32.bf16.bf16.f32 "
        "{%0,%1,%2,%3}, {%4,%5,%6,%7}, {%8,%9}, {%0,%1,%2,%3};"
        : "+f"(c[0]), "+f"(c[1]), "+f"(c[2]), "+f"(c[3])
        : "r"(a[0]), "r"(a[1]), "r"(a[2]), "r"(a[3]), "r"(b[0]), "r"(b[1]));
}

__device__ __forceinline__ double warpReduceSumD(double v) {
#pragma unroll
    for (int o = 16; o > 0; o >>= 1) v += __shfl_xor_sync(0xffffffffu, v, o);
    return v;
}
__device__ __forceinline__ float warpReduceMax(float v) {
#pragma unroll
    for (int o = 16; o > 0; o >>= 1) v = fmaxf(v, __shfl_xor_sync(0xffffffffu, v, o));
    return v;
}
__device__ __forceinline__ float silu_f(float g) {
    float sig;
    if (g >= 0.0f) {
        sig = 1.0f / (1.0f + expf(-g));
    } else {
        float e = expf(g);
        sig = e / (1.0f + e);
    }
    return g * sig;
}

// ---------------------------- small kernels --------------------------------

__global__ void zero_scalars_kernel() {
    if (threadIdx.x < 3) g_wsum[threadIdx.x] = 0.0;
}

// per-thread fp32 partial (<=16 values, rel err ~3e-10 after averaging), then double
__global__ void absum3_kernel(const float* __restrict__ W0, const float* __restrict__ W1,
                              const float* __restrict__ W2, int n4) {
    const float* W = (blockIdx.y == 0) ? W0 : (blockIdx.y == 1) ? W1 : W2;
    float s = 0.0f;
    const float4* W4 = (const float4*)W;
    for (int i = blockIdx.x * blockDim.x + threadIdx.x; i < n4;
         i += gridDim.x * blockDim.x) {
        float4 w = W4[i];
        s += (fabsf(w.x) + fabsf(w.y)) + (fabsf(w.z) + fabsf(w.w));
    }
    double d = warpReduceSumD((double)s);
    __shared__ double rs[8];
    int warp = threadIdx.x >> 5, lane = threadIdx.x & 31;
    if (lane == 0) rs[warp] = d;
    __syncthreads();
    if (threadIdx.x == 0) {
        double t = 0.0;
#pragma unroll
        for (int i = 0; i < 8; i++) t += rs[i];
        atomicAdd(&g_wsum[blockIdx.y], t);
    }
}

// ternary weight quant -> bf16 {-1,0,1}
__global__ void wquant3_kernel(const float* __restrict__ W0, const float* __restrict__ W1,
                               const float* __restrict__ W2,
                               __nv_bfloat16* __restrict__ Q0,
                               __nv_bfloat16* __restrict__ Q1,
                               __nv_bfloat16* __restrict__ Q2,
                               int n4, double inv_n) {
    const int y = blockIdx.y;
    const float* W = (y == 0) ? W0 : (y == 1) ? W1 : W2;
    __nv_bfloat16* Q = (y == 0) ? Q0 : (y == 1) ? Q1 : Q2;
    float mean = fmaxf((float)(g_wsum[y] * inv_n), 1e-5f);
    float ws = 1.0f / mean;
    int i = blockIdx.x * blockDim.x + threadIdx.x;
    if (i < n4) {
        float4 w = ((const float4*)W)[i];
        float qx = rintf(fminf(fmaxf(w.x * ws, -1.0f), 1.0f));
        float qy = rintf(fminf(fmaxf(w.y * ws, -1.0f), 1.0f));
        float qz = rintf(fminf(fmaxf(w.z * ws, -1.0f), 1.0f));
        float qw = rintf(fminf(fmaxf(w.w * ws, -1.0f), 1.0f));
        __nv_bfloat162 lo = __nv_bfloat162(__float2bfloat16(qx), __float2bfloat16(qy));
        __nv_bfloat162 hi = __nv_bfloat162(__float2bfloat16(qz), __float2bfloat16(qw));
        uint2 pk;
        pk.x = *(uint32_t*)&lo;
        pk.y = *(uint32_t*)&hi;
        ((uint2*)Q)[i] = pk;
    }
    if (i == 0) g_wdq[y] = 1.0f / ws;
}

// per-token rmsnorm + int8 absmax quant; codes emitted as bf16 (exact ints)
__global__ void __launch_bounds__(512) actquant_kernel(
        const float* __restrict__ A, __nv_bfloat16* __restrict__ Q,
        float* __restrict__ DQ, int D) {
    __shared__ float sh[8192];
    __shared__ double rs[16];
    __shared__ float rm[16];
    __shared__ float s_c, s_scale;
    const int row = blockIdx.x;
    const int n4 = D >> 2;
    const float4* a4 = (const float4*)(A + (size_t)row * D);
    float4* sh4 = (float4*)sh;
    double ss = 0.0;
    float mx = 0.0f;
    for (int i = threadIdx.x; i < n4; i += blockDim.x) {
        float4 v = a4[i];
        sh4[i] = v;
        float q = (v.x * v.x + v.y * v.y) + (v.z * v.z + v.w * v.w);
        ss += (double)q;
        mx = fmaxf(mx, fmaxf(fmaxf(fabsf(v.x), fabsf(v.y)),
                             fmaxf(fabsf(v.z), fabsf(v.w))));
    }
    ss = warpReduceSumD(ss);
    mx = warpReduceMax(mx);
    int warp = threadIdx.x >> 5, lane = threadIdx.x & 31;
    if (lane == 0) { rs[warp] = ss; rm[warp] = mx; }
    __syncthreads();
    if (threadIdx.x == 0) {
        double S = 0.0;
        float Mx = 0.0f;
#pragma unroll
        for (int i = 0; i < 16; i++) { S += rs[i]; Mx = fmaxf(Mx, rm[i]); }
        float mean = (float)(S / (double)D);
        float c = rsqrtf(mean + 1e-6f);
        float m = fmaxf(c * Mx, 1e-5f);
        float scale = 127.0f / m;
        s_c = c; s_scale = scale;
        DQ[row] = 1.0f / scale;
    }
    __syncthreads();
    const float c = s_c, scale = s_scale;
    uint2* q2 = (uint2*)(Q + (size_t)row * D);
    for (int i = threadIdx.x; i < n4; i += blockDim.x) {
        float4 v = sh4[i];
        float c0 = rintf(fminf(fmaxf((c * v.x) * scale, -128.0f), 127.0f));
        float c1 = rintf(fminf(fmaxf((c * v.y) * scale, -128.0f), 127.0f));
        float c2 = rintf(fminf(fmaxf((c * v.z) * scale, -128.0f), 127.0f));
        float c3 = rintf(fminf(fmaxf((c * v.w) * scale, -128.0f), 127.0f));
        __nv_bfloat162 lo = __nv_bfloat162(__float2bfloat16(c0), __float2bfloat16(c1));
        __nv_bfloat162 hi = __nv_bfloat162(__float2bfloat16(c2), __float2bfloat16(c3));
        uint2 pk;
        pk.x = *(uint32_t*)&lo;
        pk.y = *(uint32_t*)&hi;
        q2[i] = pk;
    }
}

// --------------------- fused gate+up bf16 HMMA GEMM ------------------------
// Block tile 128x128 of BOTH gate and up. Warps 0-3: gate (2x2 of 64x64
// warp tiles), warps 4-7: up (same tiling). Shared A tile. Epilogue:
// gate warps stage silu(g*scale) in smem; up warps multiply and write H.

__global__ void __launch_bounds__(256, 1) gateup_kernel(
        const __nv_bfloat16* __restrict__ Aq,
        const __nv_bfloat16* __restrict__ Bg,
        const __nv_bfloat16* __restrict__ Bu,
        float* __restrict__ H,
        const float* __restrict__ adq) {
    extern __shared__ __align__(128) char smem[];
    const uint32_t sbase = smem_u32(smem);
    const int tid = threadIdx.x;
    const int lane = tid & 31;
    const int g = lane >> 2, tig = lane & 3;
    const int w = tid >> 5;
    const int uw = w & 3;
    const int isUp = w >> 2;
    const int wmb = ((uw >> 1) & 1) * 64;   // warp m base within 128
    const int wnb = (uw & 1) * 64;          // warp n base within 128
    const int bm = blockIdx.y * 128, bn = blockIdx.x * 128;
    const size_t Kb = (size_t)Dd * 2;

    float acc[4][8][4];
#pragma unroll
    for (int mt = 0; mt < 4; mt++)
#pragma unroll
        for (int nt = 0; nt < 8; nt++)
#pragma unroll
            for (int k = 0; k < 4; k++) acc[mt][nt][k] = 0.0f;

    auto LOAD = [&](int kc, int s) {
        uint32_t sa = sbase + s * STG;
        const size_t kof = (size_t)kc * 128;   // bytes
        const char* Ag = (const char*)Aq + (size_t)bm * Kb + kof;
        const char* Gg = (const char*)Bg + (size_t)bn * Kb + kof;
        const char* Ug = (const char*)Bu + (size_t)bn * Kb + kof;
#pragma unroll
        for (int i = 0; i < 4; i++) {
            int idx = i * 256 + tid;
            int row = idx >> 3, ch = (idx & 7) * 16;
            cp16(sa + row * ROWB + ch, Ag + (size_t)row * Kb + ch);
        }
#pragma unroll
        for (int i = 0; i < 4; i++) {
            int idx = i * 256 + tid;
            int row = idx >> 3, ch = (idx & 7) * 16;
            cp16(sa + 18432 + row * ROWB + ch, Gg + (size_t)row * Kb + ch);
        }
#pragma unroll
        for (int i = 0; i < 4; i++) {
            int idx = i * 256 + tid;
            int row = idx >> 3, ch = (idx & 7) * 16;
            cp16(sa + 36864 + row * ROWB + ch, Ug + (size_t)row * Kb + ch);
        }
        cp_commit();
    };

    const int NK = Dd / 64;   // 32
    LOAD(0, 0); LOAD(1, 1);

    // per-lane ldmatrix address components
    const uint32_t a_row = (uint32_t)(lane & 15);
    const uint32_t a_k   = (uint32_t)((lane >> 4) * 16);
    const uint32_t b_row = (uint32_t)(((lane >> 4) << 3) + (lane & 7));
    const uint32_t b_k   = (uint32_t)(((lane >> 3) & 1) * 16);

    int cs = 0;
    for (int kc = 0; kc < NK; kc++) {
        cp_wait1();
        __syncthreads();
        int ls = cs + 2; if (ls >= 3) ls -= 3;
        if (kc + 2 < NK) LOAD(kc + 2, ls); else cp_commit();

        const uint32_t sa = sbase + cs * STG;
        const uint32_t sbW = sa + 18432 + (uint32_t)isUp * 18432;
#pragma unroll
        for (int ks = 0; ks < 4; ks++) {
            uint32_t af[4][4], bf[8][2];
#pragma unroll
            for (int mt = 0; mt < 4; mt++)
                ldsm4(af[mt], sa + (uint32_t)(wmb + mt * 16 + a_row) * ROWB
                              + (uint32_t)(ks * 32) + a_k);
#pragma unroll
            for (int p = 0; p < 4; p++) {
                uint32_t t[4];
                ldsm4(t, sbW + (uint32_t)(wnb + p * 16 + b_row) * ROWB
                         + (uint32_t)(ks * 32) + b_k);
                bf[2 * p][0] = t[0]; bf[2 * p][1] = t[1];
                bf[2 * p + 1][0] = t[2]; bf[2 * p + 1][1] = t[3];
            }
#pragma unroll
            for (int mt = 0; mt < 4; mt++)
#pragma unroll
                for (int nt = 0; nt < 8; nt++)
                    mma_bf16(acc[mt][nt], af[mt], bf[nt]);
        }
        cs++; if (cs == 3) cs = 0;
    }

    // ---- epilogue: exchange silu(g) via smem, write H = silu(g)*u ----
    __syncthreads();                 // pipeline smem free for reuse
    float* hstage = (float*)smem;    // [128][132]
    if (!isUp) {
        const float wgs = g_wdq[0];
#pragma unroll
        for (int mt = 0; mt < 4; mt++) {
            int r0 = wmb + mt * 16 + g;
            float s0 = adq[bm + r0] * wgs;
            float s1 = adq[bm + r0 + 8] * wgs;
#pragma unroll
            for (int nt = 0; nt < 8; nt++) {
                int c = wnb + nt * 8 + tig * 2;
                hstage[r0 * 132 + c]           = silu_f(acc[mt][nt][0] * s0);
                hstage[r0 * 132 + c + 1]       = silu_f(acc[mt][nt][1] * s0);
                hstage[(r0 + 8) * 132 + c]     = silu_f(acc[mt][nt][2] * s1);
                hstage[(r0 + 8) * 132 + c + 1] = silu_f(acc[mt][nt][3] * s1);
            }
        }
    }
    __syncthreads();
    if (isUp) {
        const float wus = g_wdq[1];
#pragma unroll
        for (int mt = 0; mt < 4; mt++) {
            int r0 = wmb + mt * 16 + g;
            float s0 = adq[bm + r0] * wus;
            float s1 = adq[bm + r0 + 8] * wus;
#pragma unroll
            for (int nt = 0; nt < 8; nt++) {
                int c = wnb + nt * 8 + tig * 2;
                float v00 = acc[mt][nt][0] * s0 * hstage[r0 * 132 + c];
                float v01 = acc[mt][nt][1] * s0 * hstage[r0 * 132 + c + 1];
                float v10 = acc[mt][nt][2] * s1 * hstage[(r0 + 8) * 132 + c];
                float v11 = acc[mt][nt][3] * s1 * hstage[(r0 + 8) * 132 + c + 1];
                *(float2*)&H[(size_t)(bm + r0) * Ff + bn + c] = make_float2(v00, v01);
                *(float2*)&H[(size_t)(bm + r0 + 8) * Ff + bn + c] = make_float2(v10, v11);
            }
        }
    }
}

// --------------------------- down bf16 HMMA GEMM ---------------------------
// Block 128x256, 8 warps (2x4), warp tile 64x64.

__global__ void __launch_bounds__(256, 1) down_kernel(
        const __nv_bfloat16* __restrict__ Aq, const __nv_bfloat16* __restrict__ B,
        float* __restrict__ C, int N,
        const float* __restrict__ adq, const float* __restrict__ wdq) {
    extern __shared__ __align__(128) char smem[];
    const uint32_t sbase = smem_u32(smem);
    const int tid = threadIdx.x;
    const int lane = tid & 31;
    const int g = lane >> 2, tig = lane & 3;
    const int w = tid >> 5;
    const int wmb = (w >> 2) * 64;
    const int wnb = (w & 3) * 64;
    const int bm = blockIdx.y * 128, bn = blockIdx.x * 256;
    const size_t Kb = (size_t)Ff * 2;

    float acc[4][8][4];
#pragma unroll
    for (int mt = 0; mt < 4; mt++)
#pragma unroll
        for (int nt = 0; nt < 8; nt++)
#pragma unroll
            for (int k = 0; k < 4; k++) acc[mt][nt][k] = 0.0f;

    auto LOAD = [&](int kc, int s) {
        uint32_t sa = sbase + s * STG;
        const size_t kof = (size_t)kc * 128;
        const char* Ag = (const char*)Aq + (size_t)bm * Kb + kof;
        const char* Bg2 = (const char*)B + (size_t)bn * Kb + kof;
#pragma unroll
        for (int i = 0; i < 4; i++) {
            int idx = i * 256 + tid;
            int row = idx >> 3, ch = (idx & 7) * 16;
            cp16(sa + row * ROWB + ch, Ag + (size_t)row * Kb + ch);
        }
#pragma unroll
        for (int i = 0; i < 8; i++) {
            int idx = i * 256 + tid;
            int row = idx >> 3, ch = (idx & 7) * 16;
            cp16(sa + 18432 + row * ROWB + ch, Bg2 + (size_t)row * Kb + ch);
        }
        cp_commit();
    };

    const int NK = Ff / 64;   // 128
    LOAD(0, 0); LOAD(1, 1);

    const uint32_t a_row = (uint32_t)(lane & 15);
    const uint32_t a_k   = (uint32_t)((lane >> 4) * 16);
    const uint32_t b_row = (uint32_t)(((lane >> 4) << 3) + (lane & 7));
    const uint32_t b_k   = (uint32_t)(((lane >> 3) & 1) * 16);

    int cs = 0;
    for (int kc = 0; kc < NK; kc++) {
        cp_wait1();
        __syncthreads();
        int ls = cs + 2; if (ls >= 3) ls -= 3;
        if (kc + 2 < NK) LOAD(kc + 2, ls); else cp_commit();

        const uint32_t sa = sbase + cs * STG;
        const uint32_t sb = sa + 18432;
#pragma unroll
        for (int ks = 0; ks < 4; ks++) {
            uint32_t af[4][4], bf[8][2];
#pragma unroll
            for (int mt = 0; mt < 4; mt++)
                ldsm4(af[mt], sa + (uint32_t)(wmb + mt * 16 + a_row) * ROWB
                              + (uint32_t)(ks * 32) + a_k);
#pragma unroll
            for (int p = 0; p < 4; p++) {
                uint32_t t[4];
                ldsm4(t, sb + (uint32_t)(wnb + p * 16 + b_row) * ROWB
                         + (uint32_t)(ks * 32) + b_k);
                bf[2 * p][0] = t[0]; bf[2 * p][1] = t[1];
                bf[2 * p + 1][0] = t[2]; bf[2 * p + 1][1] = t[3];
            }
#pragma unroll
            for (int mt = 0; mt < 4; mt++)
#pragma unroll
                for (int nt = 0; nt < 8; nt++)
                    mma_bf16(acc[mt][nt], af[mt], bf[nt]);
        }
        cs++; if (cs == 3) cs = 0;
    }

    const float wsc = *wdq;
#pragma unroll
    for (int mt = 0; mt < 4; mt++) {
        const int r0 = bm + wmb + mt * 16 + g;
        const int r1 = r0 + 8;
        const float s0 = adq[r0] * wsc;
        const float s1 = adq[r1] * wsc;
#pragma unroll
        for (int nt = 0; nt < 8; nt++) {
            const int c = bn + wnb + nt * 8 + tig * 2;
            *(float2*)&C[(size_t)r0 * N + c] =
                make_float2(acc[mt][nt][0] * s0, acc[mt][nt][1] * s0);
            *(float2*)&C[(size_t)r1 * N + c] =
                make_float2(acc[mt][nt][2] * s1, acc[mt][nt][3] * s1);
        }
    }
}

// ------------------------------- launch ------------------------------------

extern "C" void kernel_launch(void* const* d_in, const int* in_sizes, int n_in,
                              void* d_out, int out_size) {
    const float* x  = (const float*)d_in[0];
    const float* wg = (const float*)d_in[1];
    const float* wu = (const float*)d_in[2];
    const float* wd = (const float*)d_in[3];
    float* out = (float*)d_out;

    __nv_bfloat16 *p_wgb, *p_wub, *p_wdb, *p_xb, *p_hb;
    float *p_H, *p_xdq, *p_hdq, *p_wdq;
    cudaGetSymbolAddress((void**)&p_wgb, g_wgb);
    cudaGetSymbolAddress((void**)&p_wub, g_wub);
    cudaGetSymbolAddress((void**)&p_wdb, g_wdb);
    cudaGetSymbolAddress((void**)&p_xb,  g_xb);
    cudaGetSymbolAddress((void**)&p_hb,  g_hb);
    cudaGetSymbolAddress((void**)&p_H,   g_H);
    cudaGetSymbolAddress((void**)&p_xdq, g_xdq);
    cudaGetSymbolAddress((void**)&p_hdq, g_hdq);
    cudaGetSymbolAddress((void**)&p_wdq, g_wdq);

    cudaFuncSetAttribute(gateup_kernel,
                         cudaFuncAttributeMaxDynamicSharedMemorySize, GEMM_SMEM);
    cudaFuncSetAttribute(down_kernel,
                         cudaFuncAttributeMaxDynamicSharedMemorySize, GEMM_SMEM);

    const int nW = Ff * Dd;
    const int nW4 = nW / 4;

    zero_scalars_kernel<<<1, 32>>>();
    absum3_kernel<<<dim3(4096, 3), 256>>>(wg, wu, wd, nW4);
    wquant3_kernel<<<dim3(nW4 / 256, 3), 256>>>(wg, wu, wd, p_wgb, p_wub, p_wdb,
                                                nW4, 1.0 / (double)nW);

    actquant_kernel<<<Mm, 512>>>(x, p_xb, p_xdq, Dd);

    // fused gate+up: H = silu(gate)*up   [4096, 8192]
    gateup_kernel<<<dim3(Ff / 128, Mm / 128), 256, GEMM_SMEM>>>(
        p_xb, p_wgb, p_wub, p_H, p_xdq);

    actquant_kernel<<<Mm, 512>>>(p_H, p_hb, p_hdq, Ff);

    // down -> d_out  [4096, 2048]
    down_kernel<<<dim3(Dd / 256, Mm / 128), 256, GEMM_SMEM>>>(
        p_hb, p_wdb, out, Dd, p_hdq, p_wdq + 2);
}

// round 10
// speedup vs baseline: 1.2714x; 1.2714x over previous
#include <cuda_runtime.h>
#include <cuda_bf16.h>
#include <math.h>
#include <stdint.h>

// ---------------------------------------------------------------------------
// BitNet b1.58 MLP, exact-integer formulation on legacy bf16 HMMA.
// R9 -> R10: back to 64x32 warp tiles (2 CTAs/SM, launch_bounds(256,2)) with
// ldmatrix kept; fused gate+up kernel retained at 128x64-per-matrix tiles;
// register-resident actquant kernels (no big smem buffer, no second pass).
// GEMM arithmetic exact-integer in bf16/fp32 (codes in [-128,127], ternary
// weights, fp32 accum of ints < 2^24) -- identical results to R8/R9.
// Known floor: legacy mma.sync HMMA on the plain sm_103 ptxas target runs at
// ~1/8 tcgen05 rate => GEMMs ~1.4 ms; this round recovers occupancy + trims
// the elementwise passes.
// ---------------------------------------------------------------------------

#define Dd 2048
#define Ff 8192
#define Mm 4096

#define ROWB 144                 // 64 bf16 = 128B data + 16B pad
#define STG  36864               // 256 rows * 144B per pipeline stage
#define GEMM_SMEM (3 * STG)      // 110592 -> 2 CTAs/SM

__device__ __align__(128) __nv_bfloat16 g_wgb[Ff * Dd];
__device__ __align__(128) __nv_bfloat16 g_wub[Ff * Dd];
__device__ __align__(128) __nv_bfloat16 g_wdb[Dd * Ff];
__device__ __align__(128) __nv_bfloat16 g_xb[Mm * Dd];
__device__ __align__(128) __nv_bfloat16 g_hb[(size_t)Mm * Ff];
__device__ __align__(128) float g_H[(size_t)Mm * Ff];
__device__ float  g_xdq[Mm];
__device__ float  g_hdq[Mm];
__device__ double g_wsum[3];
__device__ float  g_wdq[3];

// ------------------------------ utilities ----------------------------------

__device__ __forceinline__ uint32_t smem_u32(const void* p) {
    uint32_t a;
    asm("{ .reg .u64 t; cvta.to.shared.u64 t, %1; cvt.u32.u64 %0, t; }"
        : "=r"(a) : "l"(p));
    return a;
}
__device__ __forceinline__ void cp16(uint32_t dst, const void* src) {
    asm volatile("cp.async.cg.shared.global [%0], [%1], 16;"
                 :: "r"(dst), "l"(src) : "memory");
}
__device__ __forceinline__ void cp_commit() {
    asm volatile("cp.async.commit_group;" ::: "memory");
}
__device__ __forceinline__ void cp_wait1() {
    asm volatile("cp.async.wait_group 1;" ::: "memory");
}
__device__ __forceinline__ void ldsm4(uint32_t* r, uint32_t addr) {
    asm volatile("ldmatrix.sync.aligned.m8n8.x4.shared.b16 {%0,%1,%2,%3}, [%4];"
                 : "=r"(r[0]), "=r"(r[1]), "=r"(r[2]), "=r"(r[3]) : "r"(addr));
}
__device__ __forceinline__ void mma_bf16(float* c, const uint32_t* a, const uint32_t* b) {
    asm volatile(
        "mma.sync.aligned.m16n8k16.row.col.f32.bf16.bf16.f32 "
        "{%0,%1,%2,%3}, {%4,%5,%6,%7}, {%8,%9}, {%0,%1,%2,%3};"
        : "+f"(c[0]), "+f"(c[1]), "+f"(c[2]), "+f"(c[3])
        : "r"(a[0]), "r"(a[1]), "r"(a[2]), "r"(a[3]), "r"(b[0]), "r"(b[1]));
}

__device__ __forceinline__ double warpReduceSumD(double v) {
#pragma unroll
    for (int o = 16; o > 0; o >>= 1) v += __shfl_xor_sync(0xffffffffu, v, o);
    return v;
}
__device__ __forceinline__ float warpReduceMax(float v) {
#pragma unroll
    for (int o = 16; o > 0; o >>= 1) v = fmaxf(v, __shfl_xor_sync(0xffffffffu, v, o));
    return v;
}
__device__ __forceinline__ float silu_f(float g) {
    float sig;
    if (g >= 0.0f) {
        sig = 1.0f / (1.0f + expf(-g));
    } else {
        float e = expf(g);
        sig = e / (1.0f + e);
    }
    return g * sig;
}

// ---------------------------- small kernels --------------------------------

__global__ void zero_scalars_kernel() {
    if (threadIdx.x < 3) g_wsum[threadIdx.x] = 0.0;
}

__global__ void absum3_kernel(const float* __restrict__ W0, const float* __restrict__ W1,
                              const float* __restrict__ W2, int n4) {
    const float* W = (blockIdx.y == 0) ? W0 : (blockIdx.y == 1) ? W1 : W2;
    float s = 0.0f;
    const float4* W4 = (const float4*)W;
    for (int i = blockIdx.x * blockDim.x + threadIdx.x; i < n4;
         i += gridDim.x * blockDim.x) {
        float4 w = W4[i];
        s += (fabsf(w.x) + fabsf(w.y)) + (fabsf(w.z) + fabsf(w.w));
    }
    double d = warpReduceSumD((double)s);
    __shared__ double rs[8];
    int warp = threadIdx.x >> 5, lane = threadIdx.x & 31;
    if (lane == 0) rs[warp] = d;
    __syncthreads();
    if (threadIdx.x == 0) {
        double t = 0.0;
#pragma unroll
        for (int i = 0; i < 8; i++) t += rs[i];
        atomicAdd(&g_wsum[blockIdx.y], t);
    }
}

__global__ void wquant3_kernel(const float* __restrict__ W0, const float* __restrict__ W1,
                               const float* __restrict__ W2,
                               __nv_bfloat16* __restrict__ Q0,
                               __nv_bfloat16* __restrict__ Q1,
                               __nv_bfloat16* __restrict__ Q2,
                               int n4, double inv_n) {
    const int y = blockIdx.y;
    const float* W = (y == 0) ? W0 : (y == 1) ? W1 : W2;
    __nv_bfloat16* Q = (y == 0) ? Q0 : (y == 1) ? Q1 : Q2;
    float mean = fmaxf((float)(g_wsum[y] * inv_n), 1e-5f);
    float ws = 1.0f / mean;
    int i = blockIdx.x * blockDim.x + threadIdx.x;
    if (i < n4) {
        float4 w = ((const float4*)W)[i];
        float qx = rintf(fminf(fmaxf(w.x * ws, -1.0f), 1.0f));
        float qy = rintf(fminf(fmaxf(w.y * ws, -1.0f), 1.0f));
        float qz = rintf(fminf(fmaxf(w.z * ws, -1.0f), 1.0f));
        float qw = rintf(fminf(fmaxf(w.w * ws, -1.0f), 1.0f));
        __nv_bfloat162 lo = __nv_bfloat162(__float2bfloat16(qx), __float2bfloat16(qy));
        __nv_bfloat162 hi = __nv_bfloat162(__float2bfloat16(qz), __float2bfloat16(qw));
        uint2 pk;
        pk.x = *(uint32_t*)&lo;
        pk.y = *(uint32_t*)&hi;
        ((uint2*)Q)[i] = pk;
    }
    if (i == 0) g_wdq[y] = 1.0f / ws;
}

// warp-per-row rmsnorm+quant for D=2048 (row held in registers, no smem)
__global__ void __launch_bounds__(256) actquant_x_kernel(
        const float* __restrict__ A, __nv_bfloat16* __restrict__ Q,
        float* __restrict__ DQ) {
    const int lane = threadIdx.x & 31;
    const int row = blockIdx.x * 8 + (threadIdx.x >> 5);
    const float4* a4 = (const float4*)(A + (size_t)row * Dd);
    uint2* q2 = (uint2*)(Q + (size_t)row * Dd);

    float4 v[16];
    double ss = 0.0;
    float mx = 0.0f;
#pragma unroll
    for (int p = 0; p < 16; p++) {
        v[p] = a4[p * 32 + lane];
        float q = (v[p].x * v[p].x + v[p].y * v[p].y)
                + (v[p].z * v[p].z + v[p].w * v[p].w);
        ss += (double)q;
        mx = fmaxf(mx, fmaxf(fmaxf(fabsf(v[p].x), fabsf(v[p].y)),
                             fmaxf(fabsf(v[p].z), fabsf(v[p].w))));
    }
    ss = warpReduceSumD(ss);
    mx = warpReduceMax(mx);
    float mean = (float)(ss / (double)Dd);
    float c = rsqrtf(mean + 1e-6f);
    float m = fmaxf(c * mx, 1e-5f);
    float scale = 127.0f / m;
    if (lane == 0) DQ[row] = 1.0f / scale;
#pragma unroll
    for (int p = 0; p < 16; p++) {
        float c0 = rintf(fminf(fmaxf((c * v[p].x) * scale, -128.0f), 127.0f));
        float c1 = rintf(fminf(fmaxf((c * v[p].y) * scale, -128.0f), 127.0f));
        float c2 = rintf(fminf(fmaxf((c * v[p].z) * scale, -128.0f), 127.0f));
        float c3 = rintf(fminf(fmaxf((c * v[p].w) * scale, -128.0f), 127.0f));
        __nv_bfloat162 lo = __nv_bfloat162(__float2bfloat16(c0), __float2bfloat16(c1));
        __nv_bfloat162 hi = __nv_bfloat162(__float2bfloat16(c2), __float2bfloat16(c3));
        uint2 pk;
        pk.x = *(uint32_t*)&lo;
        pk.y = *(uint32_t*)&hi;
        q2[p * 32 + lane] = pk;
    }
}

// block-per-row rmsnorm+quant for F=8192 (32 floats/thread in registers)
__global__ void __launch_bounds__(256) actquant_h_kernel(
        const float* __restrict__ A, __nv_bfloat16* __restrict__ Q,
        float* __restrict__ DQ) {
    __shared__ double rs[8];
    __shared__ float rm[8];
    __shared__ float s_c, s_scale;
    const int tid = threadIdx.x;
    const int row = blockIdx.x;
    const float4* a4 = (const float4*)(A + (size_t)row * Ff);
    uint2* q2 = (uint2*)(Q + (size_t)row * Ff);

    float4 v[8];
    double ss = 0.0;
    float mx = 0.0f;
#pragma unroll
    for (int p = 0; p < 8; p++) {
        v[p] = a4[p * 256 + tid];
        float q = (v[p].x * v[p].x + v[p].y * v[p].y)
                + (v[p].z * v[p].z + v[p].w * v[p].w);
        ss += (double)q;
        mx = fmaxf(mx, fmaxf(fmaxf(fabsf(v[p].x), fabsf(v[p].y)),
                             fmaxf(fabsf(v[p].z), fabsf(v[p].w))));
    }
    ss = warpReduceSumD(ss);
    mx = warpReduceMax(mx);
    int warp = tid >> 5, lane = tid & 31;
    if (lane == 0) { rs[warp] = ss; rm[warp] = mx; }
    __syncthreads();
    if (tid == 0) {
        double S = 0.0;
        float Mx = 0.0f;
#pragma unroll
        for (int i = 0; i < 8; i++) { S += rs[i]; Mx = fmaxf(Mx, rm[i]); }
        float mean = (float)(S / (double)Ff);
        float c = rsqrtf(mean + 1e-6f);
        float m = fmaxf(c * Mx, 1e-5f);
        float scale = 127.0f / m;
        s_c = c; s_scale = scale;
        DQ[row] = 1.0f / scale;
    }
    __syncthreads();
    const float c = s_c, scale = s_scale;
#pragma unroll
    for (int p = 0; p < 8; p++) {
        float c0 = rintf(fminf(fmaxf((c * v[p].x) * scale, -128.0f), 127.0f));
        float c1 = rintf(fminf(fmaxf((c * v[p].y) * scale, -128.0f), 127.0f));
        float c2 = rintf(fminf(fmaxf((c * v[p].z) * scale, -128.0f), 127.0f));
        float c3 = rintf(fminf(fmaxf((c * v[p].w) * scale, -128.0f), 127.0f));
        __nv_bfloat162 lo = __nv_bfloat162(__float2bfloat16(c0), __float2bfloat16(c1));
        __nv_bfloat162 hi = __nv_bfloat162(__float2bfloat16(c2), __float2bfloat16(c3));
        uint2 pk;
        pk.x = *(uint32_t*)&lo;
        pk.y = *(uint32_t*)&hi;
        q2[p * 256 + tid] = pk;
    }
}

// --------------------- fused gate+up bf16 HMMA GEMM ------------------------
// Block computes a 128x64 tile of BOTH gate and up (shared A tile).
// Warps 0-3: gate, warps 4-7: up; warp grid 2x2 within group, warp tile
// 64x32 (acc 64 regs -> 2 CTAs/SM). Epilogue: gate warps stage silu(g)
// in smem; up warps multiply and write H.

__global__ void __launch_bounds__(256, 2) gateup_kernel(
        const __nv_bfloat16* __restrict__ Aq,
        const __nv_bfloat16* __restrict__ Bg,
        const __nv_bfloat16* __restrict__ Bu,
        float* __restrict__ H,
        const float* __restrict__ adq) {
    extern __shared__ __align__(128) char smem[];
    const uint32_t sbase = smem_u32(smem);
    const int tid = threadIdx.x;
    const int lane = tid & 31;
    const int g = lane >> 2, tig = lane & 3;
    const int w = tid >> 5;
    const int uw = w & 3;
    const int isUp = w >> 2;
    const int wmb = (uw >> 1) * 64;       // 0 or 64
    const int wnb = (uw & 1) * 32;        // 0 or 32
    const int bm = blockIdx.y * 128, bn = blockIdx.x * 64;
    const size_t Kb = (size_t)Dd * 2;

    float acc[4][4][4];
#pragma unroll
    for (int mt = 0; mt < 4; mt++)
#pragma unroll
        for (int nt = 0; nt < 4; nt++)
#pragma unroll
            for (int k = 0; k < 4; k++) acc[mt][nt][k] = 0.0f;

    auto LOAD = [&](int kc, int s) {
        uint32_t sa = sbase + s * STG;
        const size_t kof = (size_t)kc * 128;   // bytes
        const char* Ag = (const char*)Aq + (size_t)bm * Kb + kof;
        const char* Gg = (const char*)Bg + (size_t)bn * Kb + kof;
        const char* Ug = (const char*)Bu + (size_t)bn * Kb + kof;
#pragma unroll
        for (int i = 0; i < 4; i++) {
            int idx = i * 256 + tid;
            int row = idx >> 3, ch = (idx & 7) * 16;
            cp16(sa + row * ROWB + ch, Ag + (size_t)row * Kb + ch);
        }
#pragma unroll
        for (int i = 0; i < 2; i++) {
            int idx = i * 256 + tid;
            int row = idx >> 3, ch = (idx & 7) * 16;
            cp16(sa + 18432 + row * ROWB + ch, Gg + (size_t)row * Kb + ch);
        }
#pragma unroll
        for (int i = 0; i < 2; i++) {
            int idx = i * 256 + tid;
            int row = idx >> 3, ch = (idx & 7) * 16;
            cp16(sa + 27648 + row * ROWB + ch, Ug + (size_t)row * Kb + ch);
        }
        cp_commit();
    };

    const int NK = Dd / 64;   // 32
    LOAD(0, 0); LOAD(1, 1);

    const uint32_t a_row = (uint32_t)(lane & 15);
    const uint32_t a_k   = (uint32_t)((lane >> 4) * 16);
    const uint32_t b_row = (uint32_t)(((lane >> 4) << 3) + (lane & 7));
    const uint32_t b_k   = (uint32_t)(((lane >> 3) & 1) * 16);

    int cs = 0;
    for (int kc = 0; kc < NK; kc++) {
        cp_wait1();
        __syncthreads();
        int ls = cs + 2; if (ls >= 3) ls -= 3;
        if (kc + 2 < NK) LOAD(kc + 2, ls); else cp_commit();

        const uint32_t sa = sbase + cs * STG;
        const uint32_t sbW = sa + 18432 + (uint32_t)isUp * 9216;
#pragma unroll
        for (int ks = 0; ks < 4; ks++) {
            uint32_t af[4][4], bf[4][2];
#pragma unroll
            for (int mt = 0; mt < 4; mt++)
                ldsm4(af[mt], sa + (uint32_t)(wmb + mt * 16 + a_row) * ROWB
                              + (uint32_t)(ks * 32) + a_k);
#pragma unroll
            for (int p = 0; p < 2; p++) {
                uint32_t t[4];
                ldsm4(t, sbW + (uint32_t)(wnb + p * 16 + b_row) * ROWB
                         + (uint32_t)(ks * 32) + b_k);
                bf[2 * p][0] = t[0]; bf[2 * p][1] = t[1];
                bf[2 * p + 1][0] = t[2]; bf[2 * p + 1][1] = t[3];
            }
#pragma unroll
            for (int mt = 0; mt < 4; mt++)
#pragma unroll
                for (int nt = 0; nt < 4; nt++)
                    mma_bf16(acc[mt][nt], af[mt], bf[nt]);
        }
        cs++; if (cs == 3) cs = 0;
    }

    // ---- epilogue: exchange silu(g) via smem, write H = silu(g)*u ----
    __syncthreads();
    float* hstage = (float*)smem;    // [128][68]
    if (!isUp) {
        const float wgs = g_wdq[0];
#pragma unroll
        for (int mt = 0; mt < 4; mt++) {
            int r0 = wmb + mt * 16 + g;
            float s0 = adq[bm + r0] * wgs;
            float s1 = adq[bm + r0 + 8] * wgs;
#pragma unroll
            for (int nt = 0; nt < 4; nt++) {
                int c = wnb + nt * 8 + tig * 2;
                hstage[r0 * 68 + c]           = silu_f(acc[mt][nt][0] * s0);
                hstage[r0 * 68 + c + 1]       = silu_f(acc[mt][nt][1] * s0);
                hstage[(r0 + 8) * 68 + c]     = silu_f(acc[mt][nt][2] * s1);
                hstage[(r0 + 8) * 68 + c + 1] = silu_f(acc[mt][nt][3] * s1);
            }
        }
    }
    __syncthreads();
    if (isUp) {
        const float wus = g_wdq[1];
#pragma unroll
        for (int mt = 0; mt < 4; mt++) {
            int r0 = wmb + mt * 16 + g;
            float s0 = adq[bm + r0] * wus;
            float s1 = adq[bm + r0 + 8] * wus;
#pragma unroll
            for (int nt = 0; nt < 4; nt++) {
                int c = wnb + nt * 8 + tig * 2;
                float v00 = acc[mt][nt][0] * s0 * hstage[r0 * 68 + c];
                float v01 = acc[mt][nt][1] * s0 * hstage[r0 * 68 + c + 1];
                float v10 = acc[mt][nt][2] * s1 * hstage[(r0 + 8) * 68 + c];
                float v11 = acc[mt][nt][3] * s1 * hstage[(r0 + 8) * 68 + c + 1];
                *(float2*)&H[(size_t)(bm + r0) * Ff + bn + c] = make_float2(v00, v01);
                *(float2*)&H[(size_t)(bm + r0 + 8) * Ff + bn + c] = make_float2(v10, v11);
            }
        }
    }
}

// --------------------------- down bf16 HMMA GEMM ---------------------------
// Block 128x128, 8 warps (2x4), warp tile 64x32.

__global__ void __launch_bounds__(256, 2) down_kernel(
        const __nv_bfloat16* __restrict__ Aq, const __nv_bfloat16* __restrict__ B,
        float* __restrict__ C, int N,
        const float* __restrict__ adq, const float* __restrict__ wdq) {
    extern __shared__ __align__(128) char smem[];
    const uint32_t sbase = smem_u32(smem);
    const int tid = threadIdx.x;
    const int lane = tid & 31;
    const int g = lane >> 2, tig = lane & 3;
    const int w = tid >> 5;
    const int wmb = (w >> 2) * 64;
    const int wnb = (w & 3) * 32;
    const int bm = blockIdx.y * 128, bn = blockIdx.x * 128;
    const size_t Kb = (size_t)Ff * 2;

    float acc[4][4][4];
#pragma unroll
    for (int mt = 0; mt < 4; mt++)
#pragma unroll
        for (int nt = 0; nt < 4; nt++)
#pragma unroll
            for (int k = 0; k < 4; k++) acc[mt][nt][k] = 0.0f;

    auto LOAD = [&](int kc, int s) {
        uint32_t sa = sbase + s * STG;
        const size_t kof = (size_t)kc * 128;
        const char* Ag = (const char*)Aq + (size_t)bm * Kb + kof;
        const char* Bg2 = (const char*)B + (size_t)bn * Kb + kof;
#pragma unroll
        for (int i = 0; i < 4; i++) {
            int idx = i * 256 + tid;
            int row = idx >> 3, ch = (idx & 7) * 16;
            cp16(sa + row * ROWB + ch, Ag + (size_t)row * Kb + ch);
        }
#pragma unroll
        for (int i = 0; i < 4; i++) {
            int idx = i * 256 + tid;
            int row = idx >> 3, ch = (idx & 7) * 16;
            cp16(sa + 18432 + row * ROWB + ch, Bg2 + (size_t)row * Kb + ch);
        }
        cp_commit();
    };

    const int NK = Ff / 64;   // 128
    LOAD(0, 0); LOAD(1, 1);

    const uint32_t a_row = (uint32_t)(lane & 15);
    const uint32_t a_k   = (uint32_t)((lane >> 4) * 16);
    const uint32_t b_row = (uint32_t)(((lane >> 4) << 3) + (lane & 7));
    const uint32_t b_k   = (uint32_t)(((lane >> 3) & 1) * 16);

    int cs = 0;
    for (int kc = 0; kc < NK; kc++) {
        cp_wait1();
        __syncthreads();
        int ls = cs + 2; if (ls >= 3) ls -= 3;
        if (kc + 2 < NK) LOAD(kc + 2, ls); else cp_commit();

        const uint32_t sa = sbase + cs * STG;
        const uint32_t sb = sa + 18432;
#pragma unroll
        for (int ks = 0; ks < 4; ks++) {
            uint32_t af[4][4], bf[4][2];
#pragma unroll
            for (int mt = 0; mt < 4; mt++)
                ldsm4(af[mt], sa + (uint32_t)(wmb + mt * 16 + a_row) * ROWB
                              + (uint32_t)(ks * 32) + a_k);
#pragma unroll
            for (int p = 0; p < 2; p++) {
                uint32_t t[4];
                ldsm4(t, sb + (uint32_t)(wnb + p * 16 + b_row) * ROWB
                         + (uint32_t)(ks * 32) + b_k);
                bf[2 * p][0] = t[0]; bf[2 * p][1] = t[1];
                bf[2 * p + 1][0] = t[2]; bf[2 * p + 1][1] = t[3];
            }
#pragma unroll
            for (int mt = 0; mt < 4; mt++)
#pragma unroll
                for (int nt = 0; nt < 4; nt++)
                    mma_bf16(acc[mt][nt], af[mt], bf[nt]);
        }
        cs++; if (cs == 3) cs = 0;
    }

    const float wsc = *wdq;
#pragma unroll
    for (int mt = 0; mt < 4; mt++) {
        const int r0 = bm + wmb + mt * 16 + g;
        const int r1 = r0 + 8;
        const float s0 = adq[r0] * wsc;
        const float s1 = adq[r1] * wsc;
#pragma unroll
        for (int nt = 0; nt < 4; nt++) {
            const int c = bn + wnb + nt * 8 + tig * 2;
            *(float2*)&C[(size_t)r0 * N + c] =
                make_float2(acc[mt][nt][0] * s0, acc[mt][nt][1] * s0);
            *(float2*)&C[(size_t)r1 * N + c] =
                make_float2(acc[mt][nt][2] * s1, acc[mt][nt][3] * s1);
        }
    }
}

// ------------------------------- launch ------------------------------------

extern "C" void kernel_launch(void* const* d_in, const int* in_sizes, int n_in,
                              void* d_out, int out_size) {
    const float* x  = (const float*)d_in[0];
    const float* wg = (const float*)d_in[1];
    const float* wu = (const float*)d_in[2];
    const float* wd = (const float*)d_in[3];
    float* out = (float*)d_out;

    __nv_bfloat16 *p_wgb, *p_wub, *p_wdb, *p_xb, *p_hb;
    float *p_H, *p_xdq, *p_hdq, *p_wdq;
    cudaGetSymbolAddress((void**)&p_wgb, g_wgb);
    cudaGetSymbolAddress((void**)&p_wub, g_wub);
    cudaGetSymbolAddress((void**)&p_wdb, g_wdb);
    cudaGetSymbolAddress((void**)&p_xb,  g_xb);
    cudaGetSymbolAddress((void**)&p_hb,  g_hb);
    cudaGetSymbolAddress((void**)&p_H,   g_H);
    cudaGetSymbolAddress((void**)&p_xdq, g_xdq);
    cudaGetSymbolAddress((void**)&p_hdq, g_hdq);
    cudaGetSymbolAddress((void**)&p_wdq, g_wdq);

    cudaFuncSetAttribute(gateup_kernel,
                         cudaFuncAttributeMaxDynamicSharedMemorySize, GEMM_SMEM);
    cudaFuncSetAttribute(down_kernel,
                         cudaFuncAttributeMaxDynamicSharedMemorySize, GEMM_SMEM);

    const int nW = Ff * Dd;
    const int nW4 = nW / 4;

    zero_scalars_kernel<<<1, 32>>>();
    absum3_kernel<<<dim3(4096, 3), 256>>>(wg, wu, wd, nW4);
    wquant3_kernel<<<dim3(nW4 / 256, 3), 256>>>(wg, wu, wd, p_wgb, p_wub, p_wdb,
                                                nW4, 1.0 / (double)nW);

    actquant_x_kernel<<<Mm / 8, 256>>>(x, p_xb, p_xdq);

    // fused gate+up: H = silu(gate)*up   [4096, 8192]
    gateup_kernel<<<dim3(Ff / 64, Mm / 128), 256, GEMM_SMEM>>>(
        p_xb, p_wgb, p_wub, p_H, p_xdq);

    actquant_h_kernel<<<Mm, 256>>>(p_H, p_hb, p_hdq);

    // down -> d_out  [4096, 2048]
    down_kernel<<<dim3(Dd / 128, Mm / 128), 256, GEMM_SMEM>>>(
        p_hb, p_wdb, out, Dd, p_hdq, p_wdq + 2);
}